// round 1
// baseline (speedup 1.0000x reference)
#include <cuda_runtime.h>
#include <math.h>

#define BATCH  4096
#define DIN    64
#define HID    256
#define NB     30
#define NDOF   7
#define OUTC   217            // NB*NDOF + NDOF
#define STEPS  500
#define LL     10
#define NS     51             // sample points (t = 0,10,...,500)
#define DTC    0.002f         // TAU/(T*L)
#define AZ     15.0f
#define AX     1.0f
#define BZ     3.75f          // AZ/4
#define SCALEV 1.0f

// scratch (static device allocations are allowed)
__device__ float g_feat[BATCH * HID];       // 4 MB
__device__ float g_out217[BATCH * OUTC];    // 3.6 MB
__device__ float g_coef[NS * 33];           // [sample][channel]: 0=const,1=y0,2=goal,3..32=forcing n

// ---------------------------------------------------------------------------
// Coefficient kernel: run the 500-step Euler recurrence once on 33 linear
// channels. Batch-independent.
// ---------------------------------------------------------------------------
__global__ void coeff_kernel(const float* __restrict__ c, const float* __restrict__ h) {
    __shared__ float sx[STEPS + 1];
    __shared__ float sS[STEPS + 1];
    __shared__ float sc[NB], sh[NB];
    const int t = threadIdx.x;
    if (t < NB) { sc[t] = c[t]; sh[t] = h[t]; }
    __syncthreads();

    // canonical system x_t, iterated exactly like the reference
    if (t == 0) {
        float x = 1.0f;
        for (int i = 1; i <= STEPS; i++) { x = x + (-AX * x) * DTC; sx[i] = x; }
    }
    __syncthreads();

    // S_i = sum_n psi_{i,n}, fully parallel over steps
    {
        int i = t + 1;
        if (i <= STEPS) {
            float x = sx[i];
            float s = 0.f;
#pragma unroll
            for (int n = 0; n < NB; n++) {
                float d = x - sc[n];
                s += expf(-sh[n] * d * d);
            }
            sS[i] = s;
        }
    }
    __syncthreads();

    // 33 channel recurrences
    if (t < 33) {
        float y = (t == 1) ? 1.f : 0.f;       // y0 channel starts at 1
        float z = (t == 0) ? 0.05f : 0.f;     // const channel carries z0 = dy0*TAU
        const bool  isF    = (t >= 3);
        const float fconst = (t == 2) ? (AZ * BZ) : 0.f;   // goal forcing
        float cn = 0.f, hn = 0.f;
        if (isF) { cn = sc[t - 3]; hn = sh[t - 3]; }

        g_coef[t] = y;  // sample 0 (t=0): y = y0 exactly via beta=1
        for (int i = 1; i <= STEPS; i++) {
            float f = fconst;
            if (isF) {
                float x = sx[i];
                float d = x - cn;
                f = expf(-hn * d * d) * (x / sS[i]);   // g_{i,n}
            }
            float dz = AZ * (BZ * (0.f - y) - z) + f;  // TAU = 1
            float yn = y + z * DTC;
            z = z + dz * DTC;
            y = yn;
            if ((i % LL) == 0) g_coef[(i / LL) * 33 + t] = y;
        }
    }
}

// ---------------------------------------------------------------------------
// GEMM1: feat = tanh(x @ W_pt + b_pt).  M=4096, N=256, K=64.
// Tiles 64x64, 256 threads, 4x4 register tile.
// ---------------------------------------------------------------------------
__global__ __launch_bounds__(256) void gemm1_kernel(const float* __restrict__ X,
                                                    const float* __restrict__ Wp,
                                                    const float* __restrict__ bp) {
    __shared__ float As[64][68];   // [m][k]
    __shared__ float Bs[64][68];   // [k][n]
    const int tid = threadIdx.x;
    const int bm = blockIdx.x * 64;
    const int bn = blockIdx.y * 64;

#pragma unroll
    for (int it = 0; it < 4; it++) {
        int id = tid + it * 256;         // 0..1023
        int m  = id >> 4;
        int k4 = (id & 15) << 2;
        float4 v = *reinterpret_cast<const float4*>(X + (bm + m) * DIN + k4);
        *reinterpret_cast<float4*>(&As[m][k4]) = v;
    }
#pragma unroll
    for (int it = 0; it < 4; it++) {
        int id = tid + it * 256;
        int k  = id >> 4;
        int n4 = (id & 15) << 2;
        float4 v = *reinterpret_cast<const float4*>(Wp + k * HID + bn + n4);
        *reinterpret_cast<float4*>(&Bs[k][n4]) = v;
    }
    __syncthreads();

    const int ty = tid >> 4, tx = tid & 15;
    float acc[4][4] = {};
#pragma unroll 16
    for (int k = 0; k < 64; k++) {
        float a0 = As[ty * 4 + 0][k];
        float a1 = As[ty * 4 + 1][k];
        float a2 = As[ty * 4 + 2][k];
        float a3 = As[ty * 4 + 3][k];
        float4 b = *reinterpret_cast<const float4*>(&Bs[k][tx * 4]);
        acc[0][0] += a0 * b.x; acc[0][1] += a0 * b.y; acc[0][2] += a0 * b.z; acc[0][3] += a0 * b.w;
        acc[1][0] += a1 * b.x; acc[1][1] += a1 * b.y; acc[1][2] += a1 * b.z; acc[1][3] += a1 * b.w;
        acc[2][0] += a2 * b.x; acc[2][1] += a2 * b.y; acc[2][2] += a2 * b.z; acc[2][3] += a2 * b.w;
        acc[3][0] += a3 * b.x; acc[3][1] += a3 * b.y; acc[3][2] += a3 * b.z; acc[3][3] += a3 * b.w;
    }

    float4 bb = *reinterpret_cast<const float4*>(bp + bn + tx * 4);
#pragma unroll
    for (int i = 0; i < 4; i++) {
        float4 o;
        o.x = tanhf(acc[i][0] + bb.x);
        o.y = tanhf(acc[i][1] + bb.y);
        o.z = tanhf(acc[i][2] + bb.z);
        o.w = tanhf(acc[i][3] + bb.w);
        *reinterpret_cast<float4*>(g_feat + (bm + ty * 4 + i) * HID + bn + tx * 4) = o;
    }
}

// ---------------------------------------------------------------------------
// GEMM2: out217 = feat @ W_last + b_last.  M=4096, N=217 (padded 224), K=256.
// Tiles 64x112, grid (64,2) = 128 blocks, 256 threads, 4x7 register tile.
// ---------------------------------------------------------------------------
__global__ __launch_bounds__(256) void gemm2_kernel(const float* __restrict__ Wl,
                                                    const float* __restrict__ bl) {
    __shared__ float As[32][68];    // [k][m]
    __shared__ float Bs[32][113];   // [k][n]
    const int tid = threadIdx.x;
    const int bm = blockIdx.x * 64;
    const int bn = blockIdx.y * 112;
    const int ty = tid >> 4, tx = tid & 15;

    float acc[4][7] = {};

    for (int k0 = 0; k0 < HID; k0 += 32) {
        __syncthreads();
        // A tile 64x32, coalesced float4 loads, transposed store
#pragma unroll
        for (int it = 0; it < 2; it++) {
            int id = tid + it * 256;     // 0..511
            int m  = id >> 3;            // 0..63
            int k4 = (id & 7) << 2;
            float4 v = *reinterpret_cast<const float4*>(g_feat + (bm + m) * HID + k0 + k4);
            As[k4 + 0][m] = v.x;
            As[k4 + 1][m] = v.y;
            As[k4 + 2][m] = v.z;
            As[k4 + 3][m] = v.w;
        }
        // B tile 32x112, guarded (N=217)
        for (int id = tid; id < 32 * 112; id += 256) {
            int kk = id / 112;
            int cc = id - kk * 112;
            int col = bn + cc;
            Bs[kk][cc] = (col < OUTC) ? Wl[(k0 + kk) * OUTC + col] : 0.f;
        }
        __syncthreads();

#pragma unroll 8
        for (int kk = 0; kk < 32; kk++) {
            float4 a = *reinterpret_cast<const float4*>(&As[kk][ty * 4]);
            float b[7];
#pragma unroll
            for (int j = 0; j < 7; j++) b[j] = Bs[kk][tx + 16 * j];
#pragma unroll
            for (int j = 0; j < 7; j++) {
                acc[0][j] += a.x * b[j];
                acc[1][j] += a.y * b[j];
                acc[2][j] += a.z * b[j];
                acc[3][j] += a.w * b[j];
            }
        }
    }

#pragma unroll
    for (int j = 0; j < 7; j++) {
        int col = bn + tx + 16 * j;
        if (col < OUTC) {
            float bb = bl[col];
#pragma unroll
            for (int i = 0; i < 4; i++) {
                g_out217[(bm + ty * 4 + i) * OUTC + col] = (acc[i][j] + bb) * SCALEV;
            }
        }
    }
}

// ---------------------------------------------------------------------------
// Rollout: one thread per (b, dof) row; y(T) = alpha + beta*y0 + gamma*goal
//          + dot(delta_T, u),  u_n = w_n * (goal - y0).
// ---------------------------------------------------------------------------
__global__ __launch_bounds__(256) void rollout_kernel(const float* __restrict__ state,
                                                      float* __restrict__ out) {
    __shared__ float scf[NS * 33];
    for (int i = threadIdx.x; i < NS * 33; i += blockDim.x) scf[i] = g_coef[i];
    __syncthreads();

    int row = blockIdx.x * blockDim.x + threadIdx.x;
    if (row >= BATCH * NDOF) return;
    int b = row / NDOF;
    int dof = row - b * NDOF;

    const float* o = g_out217 + b * OUTC;
    float y0   = state[row];
    float goal = o[dof];
    float gy0  = goal - y0;

    float u[NB];
#pragma unroll
    for (int n = 0; n < NB; n++) u[n] = o[NDOF + dof * NB + n] * gy0;

    float* op = out + (size_t)b * (NS * NDOF) + dof;
    for (int s = 0; s < NS; s++) {
        const float* cf = scf + s * 33;
        float acc = cf[0] + cf[1] * y0 + cf[2] * goal;
#pragma unroll
        for (int n = 0; n < NB; n++) acc += cf[3 + n] * u[n];
        op[s * NDOF] = acc;
    }
}

// ---------------------------------------------------------------------------
extern "C" void kernel_launch(void* const* d_in, const int* in_sizes, int n_in,
                              void* d_out, int out_size) {
    const float* x      = (const float*)d_in[0];
    const float* state  = (const float*)d_in[1];
    const float* W_pt   = (const float*)d_in[2];
    const float* b_pt   = (const float*)d_in[3];
    const float* W_last = (const float*)d_in[4];
    const float* b_last = (const float*)d_in[5];
    const float* c      = (const float*)d_in[6];
    const float* h      = (const float*)d_in[7];
    float* out = (float*)d_out;

    coeff_kernel<<<1, 512>>>(c, h);
    gemm1_kernel<<<dim3(BATCH / 64, HID / 64), 256>>>(x, W_pt, b_pt);
    gemm2_kernel<<<dim3(BATCH / 64, 2), 256>>>(W_last, b_last);
    rollout_kernel<<<(BATCH * NDOF + 255) / 256, 256>>>(state, out);
}

// round 2
// speedup vs baseline: 1.4665x; 1.4665x over previous
#include <cuda_runtime.h>
#include <math.h>

#define BATCH 4096
#define DIN   64
#define HID   256
#define NB    30
#define NDOF  7
#define OUTC  217
#define STEPS 500
#define NS    51
#define DTC   0.002f
#define AZBZ  56.25f
// ln(float(0.998)) and ln(0.985)
#define LNX   (-0.0020019769f)
#define LNLAM (-0.015113638f)

__device__ float g_feat[BATCH * HID];
__device__ float g_out217[BATCH * OUTC];
__device__ float g_coef[NS * 33];
__device__ float g_forc[(STEPS + 1) * 32];

typedef unsigned long long ull;
__device__ __forceinline__ void fma2(ull& d, ull a, ull b) {
    asm("fma.rn.f32x2 %0, %1, %2, %0;" : "+l"(d) : "l"(a), "l"(b));
}
__device__ __forceinline__ float lo32(ull v) { return __uint_as_float((unsigned)v); }
__device__ __forceinline__ float hi32(ull v) { return __uint_as_float((unsigned)(v >> 32)); }

// ---------------------------------------------------------------------------
// Forcing gains g[i][n] = psi_n(x_i) * x_i / S_i, fully parallel over i.
// ---------------------------------------------------------------------------
__global__ void forcing_kernel(const float* __restrict__ c, const float* __restrict__ h) {
    int i = blockIdx.x * blockDim.x + threadIdx.x + 1;
    if (i > STEPS) return;
    float x = expf(LNX * (float)i);
    float psi[NB];
    float S = 0.f;
#pragma unroll
    for (int n = 0; n < NB; n++) {
        float d = x - c[n];
        float p = expf(-h[n] * d * d);
        psi[n] = p;
        S += p;
    }
    float sc = x / S;
#pragma unroll
    for (int n = 0; n < NB; n++) g_forc[i * 32 + n] = psi[n] * sc;
}

// ---------------------------------------------------------------------------
// Coefficients via closed-form matrix powers: A^k = lam^k I + k lam^{k-1} N.
//   alpha_T = 0.05*dt*kw[T]; beta_T = lam^T + 0.015*kw[T];
//   gamma_T = azbz*dt^2*Sum kw[k]; delta_{T,n} = dt^2*Sum kw[k]*g[T-k][n].
// kw[k] = k*lam^{k-1}. One block per sample, 8-way split sums.
// ---------------------------------------------------------------------------
__global__ __launch_bounds__(288) void coef_kernel() {
    __shared__ float kw[STEPS + 1];
    __shared__ float red[33][9];
    int tid = threadIdx.x;
    for (int k = tid; k <= STEPS; k += 288)
        kw[k] = (k == 0) ? 0.f : (float)k * expf(LNLAM * (float)(k - 1));
    __syncthreads();

    int s = blockIdx.x;
    int T = s * 10;
    int ch = tid >> 3;
    int part = tid & 7;
    if (ch < 33) {
        float acc = 0.f;
        if (ch >= 3) {
            int n = ch - 3;
            for (int k = part; k < T; k += 8)
                acc += kw[k] * g_forc[(T - k) * 32 + n];
        } else if (ch == 2) {
            for (int k = part; k < T; k += 8) acc += kw[k];
        }
        red[ch][part] = acc;
    }
    __syncthreads();
    if (tid < 33) {
        float sum = 0.f;
#pragma unroll
        for (int p = 0; p < 8; p++) sum += red[tid][p];
        float v;
        if (tid == 0)      v = 0.05f * DTC * kw[T];
        else if (tid == 1) v = expf(LNLAM * (float)T) + 0.015f * kw[T];
        else if (tid == 2) v = AZBZ * (DTC * DTC) * sum;
        else               v = (DTC * DTC) * sum;
        g_coef[s * 33 + tid] = v;
    }
}

// ---------------------------------------------------------------------------
// GEMM1: feat = tanh(x @ W_pt + b_pt). M=4096,N=256,K=64. FFMA2 path.
// Block tile 64x64, thread tile 4x4 (2 row-pairs x 4 strided cols).
// ---------------------------------------------------------------------------
__global__ __launch_bounds__(256) void gemm1_kernel(const float* __restrict__ X,
                                                    const float* __restrict__ Wp,
                                                    const float* __restrict__ bp) {
    __shared__ float  As[64][66];   // [k][m]
    __shared__ float2 Bs[64][66];   // [k][n] duplicated
    const int tid = threadIdx.x;
    const int bm = blockIdx.x * 64;
    const int bn = blockIdx.y * 64;

#pragma unroll
    for (int it = 0; it < 4; it++) {
        int id = tid + it * 256;     // 0..1023
        int m = id >> 4, k4 = (id & 15) << 2;
        float4 v = *reinterpret_cast<const float4*>(X + (bm + m) * DIN + k4);
        As[k4 + 0][m] = v.x; As[k4 + 1][m] = v.y;
        As[k4 + 2][m] = v.z; As[k4 + 3][m] = v.w;
    }
#pragma unroll
    for (int it = 0; it < 16; it++) {
        int id = tid + it * 256;     // 0..4095
        int k = id >> 6, n = id & 63;
        float v = Wp[k * HID + bn + n];
        Bs[k][n] = make_float2(v, v);
    }
    __syncthreads();

    const int ty = tid >> 4, tx = tid & 15;
    ull acc[2][4];
#pragma unroll
    for (int i = 0; i < 2; i++)
#pragma unroll
        for (int j = 0; j < 4; j++) acc[i][j] = 0ull;

#pragma unroll
    for (int k = 0; k < 64; k++) {
        ull a0 = *reinterpret_cast<const ull*>(&As[k][ty * 4]);
        ull a1 = *reinterpret_cast<const ull*>(&As[k][ty * 4 + 2]);
#pragma unroll
        for (int j = 0; j < 4; j++) {
            ull b = *reinterpret_cast<const ull*>(&Bs[k][tx + 16 * j]);
            fma2(acc[0][j], a0, b);
            fma2(acc[1][j], a1, b);
        }
    }

#pragma unroll
    for (int j = 0; j < 4; j++) {
        int col = bn + tx + 16 * j;
        float bb = bp[col];
        int r = bm + ty * 4;
        g_feat[(r + 0) * HID + col] = tanhf(lo32(acc[0][j]) + bb);
        g_feat[(r + 1) * HID + col] = tanhf(hi32(acc[0][j]) + bb);
        g_feat[(r + 2) * HID + col] = tanhf(lo32(acc[1][j]) + bb);
        g_feat[(r + 3) * HID + col] = tanhf(hi32(acc[1][j]) + bb);
    }
}

// ---------------------------------------------------------------------------
// GEMM2: out217 = feat @ W_last + b_last. M=4096,N=217(pad 224),K=256. FFMA2.
// Block tile 64x112, grid (64,2), thread tile 4x7.
// ---------------------------------------------------------------------------
__global__ __launch_bounds__(256) void gemm2_kernel(const float* __restrict__ Wl,
                                                    const float* __restrict__ bl) {
    __shared__ float  As[32][66];    // [k][m]
    __shared__ float2 Bs[32][114];   // [k][n] duplicated
    const int tid = threadIdx.x;
    const int bm = blockIdx.x * 64;
    const int bn = blockIdx.y * 112;
    const int ty = tid >> 4, tx = tid & 15;

    ull acc[2][7];
#pragma unroll
    for (int i = 0; i < 2; i++)
#pragma unroll
        for (int j = 0; j < 7; j++) acc[i][j] = 0ull;

    for (int k0 = 0; k0 < HID; k0 += 32) {
        __syncthreads();
#pragma unroll
        for (int it = 0; it < 2; it++) {
            int id = tid + it * 256;   // 0..511
            int m = id >> 3, k4 = (id & 7) << 2;
            float4 v = *reinterpret_cast<const float4*>(g_feat + (bm + m) * HID + k0 + k4);
            As[k4 + 0][m] = v.x; As[k4 + 1][m] = v.y;
            As[k4 + 2][m] = v.z; As[k4 + 3][m] = v.w;
        }
        for (int id = tid; id < 32 * 112; id += 256) {
            int kk = id / 112, cc = id - kk * 112;
            int col = bn + cc;
            float v = (col < OUTC) ? Wl[(k0 + kk) * OUTC + col] : 0.f;
            Bs[kk][cc] = make_float2(v, v);
        }
        __syncthreads();

#pragma unroll
        for (int kk = 0; kk < 32; kk++) {
            ull a0 = *reinterpret_cast<const ull*>(&As[kk][ty * 4]);
            ull a1 = *reinterpret_cast<const ull*>(&As[kk][ty * 4 + 2]);
#pragma unroll
            for (int j = 0; j < 7; j++) {
                ull b = *reinterpret_cast<const ull*>(&Bs[kk][tx + 16 * j]);
                fma2(acc[0][j], a0, b);
                fma2(acc[1][j], a1, b);
            }
        }
    }

#pragma unroll
    for (int j = 0; j < 7; j++) {
        int col = bn + tx + 16 * j;
        if (col < OUTC) {
            float bb = bl[col];
            int r = bm + ty * 4;
            g_out217[(r + 0) * OUTC + col] = lo32(acc[0][j]) + bb;
            g_out217[(r + 1) * OUTC + col] = hi32(acc[0][j]) + bb;
            g_out217[(r + 2) * OUTC + col] = lo32(acc[1][j]) + bb;
            g_out217[(r + 3) * OUTC + col] = hi32(acc[1][j]) + bb;
        }
    }
}

// ---------------------------------------------------------------------------
// Rollout: y(b,dof,s) = sum_ch U[row][ch] * coef[s][ch].
// Block = 64 rows x 4 sample-groups of <=13. 448 blocks.
// ---------------------------------------------------------------------------
__global__ __launch_bounds__(256) void rollout_kernel(const float* __restrict__ state,
                                                      float* __restrict__ out) {
    __shared__ float su[33][64];
    __shared__ float sg[64];
    __shared__ float scf[52 * 33];   // padded (s=51 row is garbage, never stored)
    const int tid = threadIdx.x;
    const int base = blockIdx.x * 64;

    for (int i = tid; i < NS * 33; i += 256) scf[i] = g_coef[i];
    if (tid < 64) {
        int row = base + tid;
        int b = row / NDOF, dof = row - b * NDOF;
        float y0 = state[row];
        float goal = g_out217[b * OUTC + dof];
        su[0][tid] = 1.f;
        su[1][tid] = y0;
        su[2][tid] = goal;
        sg[tid] = goal - y0;
    }
    __syncthreads();
    for (int idx = tid; idx < 64 * NB; idx += 256) {
        int r = idx & 63, n = idx >> 6;          // consecutive threads -> consecutive r
        int row = base + r;
        int b = row / NDOF, dof = row - b * NDOF;
        float w = g_out217[b * OUTC + NDOF + dof * NB + n];
        su[3 + n][r] = w * sg[r];
    }
    __syncthreads();

    const int r = tid & 63;
    const int grp = tid >> 6;
    const int s0 = grp * 13;
    const int ns = (grp == 3) ? 12 : 13;

    float acc[13];
#pragma unroll
    for (int q = 0; q < 13; q++) acc[q] = 0.f;

#pragma unroll
    for (int ch = 0; ch < 33; ch++) {
        float uv = su[ch][r];
        const float* cf = scf + s0 * 33 + ch;
#pragma unroll
        for (int q = 0; q < 13; q++) acc[q] += cf[q * 33] * uv;
    }

    int row = base + r;
    int b = row / NDOF, dof = row - b * NDOF;
    float* op = out + (size_t)b * (NS * NDOF) + dof;
#pragma unroll
    for (int q = 0; q < 13; q++)
        if (q < ns) op[(s0 + q) * NDOF] = acc[q];
}

// ---------------------------------------------------------------------------
extern "C" void kernel_launch(void* const* d_in, const int* in_sizes, int n_in,
                              void* d_out, int out_size) {
    const float* x      = (const float*)d_in[0];
    const float* state  = (const float*)d_in[1];
    const float* W_pt   = (const float*)d_in[2];
    const float* b_pt   = (const float*)d_in[3];
    const float* W_last = (const float*)d_in[4];
    const float* b_last = (const float*)d_in[5];
    const float* c      = (const float*)d_in[6];
    const float* h      = (const float*)d_in[7];
    float* out = (float*)d_out;

    forcing_kernel<<<4, 128>>>(c, h);
    gemm1_kernel<<<dim3(BATCH / 64, HID / 64), 256>>>(x, W_pt, b_pt);
    gemm2_kernel<<<dim3(BATCH / 64, 2), 256>>>(W_last, b_last);
    coef_kernel<<<NS, 288>>>();
    rollout_kernel<<<BATCH * NDOF / 64, 256>>>(state, out);
}

// round 3
// speedup vs baseline: 1.8713x; 1.2760x over previous
#include <cuda_runtime.h>
#include <math.h>

#define BATCH 4096
#define DIN   64
#define HID   256
#define NB    30
#define NDOF  7
#define OUTC  217
#define STEPS 500
#define NS    51
#define DTC   0.002f
#define AZBZ  56.25f
// ln(float(0.998)) and ln(0.985)
#define LNX   (-0.0020019769f)
#define LNLAM (-0.015113638f)
#define GW    501

__device__ float g_feat[BATCH * HID];
__device__ float g_out217[BATCH * OUTC];
__device__ float g_coef[NS * 33];

typedef unsigned long long ull;
__device__ __forceinline__ void fma2(ull& d, ull a, ull b) {
    asm("fma.rn.f32x2 %0, %1, %2, %0;" : "+l"(d) : "l"(a), "l"(b));
}
__device__ __forceinline__ float lo32(ull v) { return __uint_as_float((unsigned)v); }
__device__ __forceinline__ float hi32(ull v) { return __uint_as_float((unsigned)(v >> 32)); }

// ---------------------------------------------------------------------------
// Fused forcing + coefficient kernel. One block per sample s (T = 10*s).
//   kw[k]   = k * lam^{k-1}
//   g[n][i] = psi_n(x_i) * x_i / S_i        (forcing gains, i = 1..T-1)
//   alpha_T = 0.05*dt*kw[T]
//   beta_T  = lam^T + 0.015*kw[T]
//   gamma_T = AZBZ*dt^2 * Sum_{k<T} kw[k]
//   delta_{T,n} = dt^2 * Sum_{k<T} kw[k]*g[n][T-k]
// ---------------------------------------------------------------------------
__global__ __launch_bounds__(256) void coef_kernel(const float* __restrict__ c,
                                                   const float* __restrict__ h) {
    extern __shared__ float sm[];
    float* g  = sm;                 // [NB][GW]
    float* kw = g + NB * GW;        // [GW]
    float* sc = kw + GW;            // [NB]
    float* sh = sc + NB;            // [NB]

    const int tid = threadIdx.x;
    const int s = blockIdx.x;
    const int T = s * 10;

    if (tid < NB) { sc[tid] = c[tid]; sh[tid] = h[tid]; }
    for (int k = tid; k <= T; k += 256)
        kw[k] = (k == 0) ? 0.f : (float)k * expf(LNLAM * (float)(k - 1));
    __syncthreads();

    // forcing gains for steps this sample needs (i = 1 .. T-1)
    for (int i = tid + 1; i < T; i += 256) {
        float x = expf(LNX * (float)i);
        float psi[NB];
        float S = 0.f;
#pragma unroll
        for (int n = 0; n < NB; n++) {
            float d = x - sc[n];
            float p = expf(-sh[n] * d * d);
            psi[n] = p;
            S += p;
        }
        float scale = x / S;
#pragma unroll
        for (int n = 0; n < NB; n++) g[n * GW + i] = psi[n] * scale;
    }
    __syncthreads();

    // convolution: 8 lanes per channel, shuffle-reduce
    const int n = tid >> 3;
    const int part = tid & 7;
    float acc = 0.f;
    if (n < NB) {
        const float* gn = g + n * GW;
        for (int k = part; k < T; k += 8) acc += kw[k] * gn[T - k];
    } else if (n == NB) {
        for (int k = part; k < T; k += 8) acc += kw[k];
    }
    acc += __shfl_down_sync(0xffffffffu, acc, 4, 8);
    acc += __shfl_down_sync(0xffffffffu, acc, 2, 8);
    acc += __shfl_down_sync(0xffffffffu, acc, 1, 8);

    if (part == 0) {
        if (n < NB)       g_coef[s * 33 + 3 + n] = (DTC * DTC) * acc;
        else if (n == NB) g_coef[s * 33 + 2]     = AZBZ * (DTC * DTC) * acc;
    }
    if (tid == 254) g_coef[s * 33 + 0] = 0.05f * DTC * kw[T];
    if (tid == 255) g_coef[s * 33 + 1] = expf(LNLAM * (float)T) + 0.015f * kw[T];
}

// ---------------------------------------------------------------------------
// GEMM1: feat = tanh(x @ W_pt + b_pt). M=4096,N=256,K=64. FFMA2 path.
// ---------------------------------------------------------------------------
__global__ __launch_bounds__(256) void gemm1_kernel(const float* __restrict__ X,
                                                    const float* __restrict__ Wp,
                                                    const float* __restrict__ bp) {
    __shared__ float  As[64][66];   // [k][m]
    __shared__ float2 Bs[64][66];   // [k][n] duplicated
    const int tid = threadIdx.x;
    const int bm = blockIdx.x * 64;
    const int bn = blockIdx.y * 64;

#pragma unroll
    for (int it = 0; it < 4; it++) {
        int id = tid + it * 256;
        int m = id >> 4, k4 = (id & 15) << 2;
        float4 v = *reinterpret_cast<const float4*>(X + (bm + m) * DIN + k4);
        As[k4 + 0][m] = v.x; As[k4 + 1][m] = v.y;
        As[k4 + 2][m] = v.z; As[k4 + 3][m] = v.w;
    }
#pragma unroll
    for (int it = 0; it < 4; it++) {
        int id = tid + it * 256;          // 0..1023
        int k = id >> 4, n4 = (id & 15) << 2;
        float4 v = *reinterpret_cast<const float4*>(Wp + k * HID + bn + n4);
        Bs[k][n4 + 0] = make_float2(v.x, v.x);
        Bs[k][n4 + 1] = make_float2(v.y, v.y);
        Bs[k][n4 + 2] = make_float2(v.z, v.z);
        Bs[k][n4 + 3] = make_float2(v.w, v.w);
    }
    __syncthreads();

    const int ty = tid >> 4, tx = tid & 15;
    ull acc[2][4];
#pragma unroll
    for (int i = 0; i < 2; i++)
#pragma unroll
        for (int j = 0; j < 4; j++) acc[i][j] = 0ull;

#pragma unroll
    for (int k = 0; k < 64; k++) {
        ull a0 = *reinterpret_cast<const ull*>(&As[k][ty * 4]);
        ull a1 = *reinterpret_cast<const ull*>(&As[k][ty * 4 + 2]);
#pragma unroll
        for (int j = 0; j < 4; j++) {
            ull b = *reinterpret_cast<const ull*>(&Bs[k][tx + 16 * j]);
            fma2(acc[0][j], a0, b);
            fma2(acc[1][j], a1, b);
        }
    }

#pragma unroll
    for (int j = 0; j < 4; j++) {
        int col = bn + tx + 16 * j;
        float bb = bp[col];
        int r = bm + ty * 4;
        g_feat[(r + 0) * HID + col] = tanhf(lo32(acc[0][j]) + bb);
        g_feat[(r + 1) * HID + col] = tanhf(hi32(acc[0][j]) + bb);
        g_feat[(r + 2) * HID + col] = tanhf(lo32(acc[1][j]) + bb);
        g_feat[(r + 3) * HID + col] = tanhf(hi32(acc[1][j]) + bb);
    }
}

// ---------------------------------------------------------------------------
// GEMM2: out217 = feat @ W_last + b_last. M=4096,N=217(pad 224),K=256.
// FFMA2, register-staged double buffering over 8 K-tiles of 32.
// ---------------------------------------------------------------------------
__global__ __launch_bounds__(256) void gemm2_kernel(const float* __restrict__ Wl,
                                                    const float* __restrict__ bl) {
    __shared__ float  As[32][66];    // [k][m]
    __shared__ float2 Bs[32][114];   // [k][n] duplicated
    const int tid = threadIdx.x;
    const int bm = blockIdx.x * 64;
    const int bn = blockIdx.y * 112;
    const int ty = tid >> 4, tx = tid & 15;

    // precomputed B load coordinates (fixed across tiles)
    int bkk[14], bcc[14];
    bool bok[14];
#pragma unroll
    for (int it = 0; it < 14; it++) {
        int id = tid + it * 256;
        bkk[it] = id / 112;
        bcc[it] = id - bkk[it] * 112;
        bok[it] = (bn + bcc[it]) < OUTC;
    }
    const int am = tid >> 3;                 // A row within 0..31 group; two loads
    const int ak4 = (tid & 7) << 2;

    float4 ra[2];
    float rb[14];

    // prologue: load tile 0
#pragma unroll
    for (int it = 0; it < 2; it++)
        ra[it] = *reinterpret_cast<const float4*>(g_feat + (bm + am + it * 32) * HID + ak4);
#pragma unroll
    for (int it = 0; it < 14; it++)
        rb[it] = bok[it] ? Wl[bkk[it] * OUTC + bn + bcc[it]] : 0.f;

    ull acc[2][7];
#pragma unroll
    for (int i = 0; i < 2; i++)
#pragma unroll
        for (int j = 0; j < 7; j++) acc[i][j] = 0ull;

    for (int k0 = 0; k0 < HID; k0 += 32) {
        // stage current regs -> smem
#pragma unroll
        for (int it = 0; it < 2; it++) {
            int m = am + it * 32;
            As[ak4 + 0][m] = ra[it].x; As[ak4 + 1][m] = ra[it].y;
            As[ak4 + 2][m] = ra[it].z; As[ak4 + 3][m] = ra[it].w;
        }
#pragma unroll
        for (int it = 0; it < 14; it++)
            Bs[bkk[it]][bcc[it]] = make_float2(rb[it], rb[it]);
        __syncthreads();

        // prefetch next tile into regs
        if (k0 + 32 < HID) {
#pragma unroll
            for (int it = 0; it < 2; it++)
                ra[it] = *reinterpret_cast<const float4*>(
                    g_feat + (bm + am + it * 32) * HID + k0 + 32 + ak4);
#pragma unroll
            for (int it = 0; it < 14; it++)
                rb[it] = bok[it] ? Wl[(k0 + 32 + bkk[it]) * OUTC + bn + bcc[it]] : 0.f;
        }

        // compute
#pragma unroll
        for (int kk = 0; kk < 32; kk++) {
            ull a0 = *reinterpret_cast<const ull*>(&As[kk][ty * 4]);
            ull a1 = *reinterpret_cast<const ull*>(&As[kk][ty * 4 + 2]);
#pragma unroll
            for (int j = 0; j < 7; j++) {
                ull b = *reinterpret_cast<const ull*>(&Bs[kk][tx + 16 * j]);
                fma2(acc[0][j], a0, b);
                fma2(acc[1][j], a1, b);
            }
        }
        __syncthreads();
    }

#pragma unroll
    for (int j = 0; j < 7; j++) {
        int col = bn + tx + 16 * j;
        if (col < OUTC) {
            float bb = bl[col];
            int r = bm + ty * 4;
            g_out217[(r + 0) * OUTC + col] = lo32(acc[0][j]) + bb;
            g_out217[(r + 1) * OUTC + col] = hi32(acc[0][j]) + bb;
            g_out217[(r + 2) * OUTC + col] = lo32(acc[1][j]) + bb;
            g_out217[(r + 3) * OUTC + col] = hi32(acc[1][j]) + bb;
        }
    }
}

// ---------------------------------------------------------------------------
// Rollout: y(b,dof,s) = sum_ch U[row][ch] * coef[s][ch].
// ---------------------------------------------------------------------------
__global__ __launch_bounds__(256) void rollout_kernel(const float* __restrict__ state,
                                                      float* __restrict__ out) {
    __shared__ float su[33][64];
    __shared__ float sg[64];
    __shared__ float scf[52 * 33];
    const int tid = threadIdx.x;
    const int base = blockIdx.x * 64;

    for (int i = tid; i < NS * 33; i += 256) scf[i] = g_coef[i];
    if (tid < 64) {
        int row = base + tid;
        int b = row / NDOF, dof = row - b * NDOF;
        float y0 = state[row];
        float goal = g_out217[b * OUTC + dof];
        su[0][tid] = 1.f;
        su[1][tid] = y0;
        su[2][tid] = goal;
        sg[tid] = goal - y0;
    }
    __syncthreads();
    for (int idx = tid; idx < 64 * NB; idx += 256) {
        int r = idx & 63, n = idx >> 6;
        int row = base + r;
        int b = row / NDOF, dof = row - b * NDOF;
        float w = g_out217[b * OUTC + NDOF + dof * NB + n];
        su[3 + n][r] = w * sg[r];
    }
    __syncthreads();

    const int r = tid & 63;
    const int grp = tid >> 6;
    const int s0 = grp * 13;
    const int ns = (grp == 3) ? 12 : 13;

    float acc[13];
#pragma unroll
    for (int q = 0; q < 13; q++) acc[q] = 0.f;

#pragma unroll
    for (int ch = 0; ch < 33; ch++) {
        float uv = su[ch][r];
        const float* cf = scf + s0 * 33 + ch;
#pragma unroll
        for (int q = 0; q < 13; q++) acc[q] += cf[q * 33] * uv;
    }

    int row = base + r;
    int b = row / NDOF, dof = row - b * NDOF;
    float* op = out + (size_t)b * (NS * NDOF) + dof;
#pragma unroll
    for (int q = 0; q < 13; q++)
        if (q < ns) op[(s0 + q) * NDOF] = acc[q];
}

// ---------------------------------------------------------------------------
extern "C" void kernel_launch(void* const* d_in, const int* in_sizes, int n_in,
                              void* d_out, int out_size) {
    const float* x      = (const float*)d_in[0];
    const float* state  = (const float*)d_in[1];
    const float* W_pt   = (const float*)d_in[2];
    const float* b_pt   = (const float*)d_in[3];
    const float* W_last = (const float*)d_in[4];
    const float* b_last = (const float*)d_in[5];
    const float* c      = (const float*)d_in[6];
    const float* h      = (const float*)d_in[7];
    float* out = (float*)d_out;

    const int coef_smem = (NB * GW + GW + 2 * NB) * (int)sizeof(float);
    static int attr_done = 0;
    if (!attr_done) {
        cudaFuncSetAttribute(coef_kernel, cudaFuncAttributeMaxDynamicSharedMemorySize,
                             coef_smem);
        attr_done = 1;
    }

    coef_kernel<<<NS, 256, coef_smem>>>(c, h);
    gemm1_kernel<<<dim3(BATCH / 64, HID / 64), 256>>>(x, W_pt, b_pt);
    gemm2_kernel<<<dim3(BATCH / 64, 2), 256>>>(W_last, b_last);
    rollout_kernel<<<BATCH * NDOF / 64, 256>>>(state, out);
}